// round 1
// baseline (speedup 1.0000x reference)
#include <cuda_runtime.h>
#include <math.h>

// Problem constants
constexpr int B = 2, S = 2048, D = 1024, H = 16, DH = 64;
constexpr int MROWS = B * S;          // 4096
constexpr int NBH = B * H;            // 32
constexpr long OUT_ELEMS = (long)B * S * D;   // 4,194,304

// Scratch (device globals -> no allocation)
__device__ float g_qp[NBH * S * DH];      // 16 MB, [bh][s][dh]
__device__ float g_kp[NBH * S * DH];
__device__ float g_vp[NBH * S * DH];
__device__ float g_attn[MROWS * D];       // 16 MB, [b][s][d]

// ---------------------------------------------------------------------------
// SGEMM with bias: Y = X @ W^T + b.  X:[M=4096,K=1024], W:[N=1024,K=1024].
// split=1 -> write split-head layout [B,H,S,DH]; split=0 -> [M,N] row-major.
// 128x128 tile, BK=8, 256 threads, 8x8 micro-tile (cols split 4+4 for LDS).
// ---------------------------------------------------------------------------
__global__ __launch_bounds__(256) void sgemm_bias_kernel(
    const float* __restrict__ X, const float* __restrict__ W,
    const float* __restrict__ bias, float* __restrict__ Y, int split)
{
    __shared__ float As[8][132];
    __shared__ float Bs[8][132];
    const int tid = threadIdx.x;
    const int bn = blockIdx.x, bm = blockIdx.y;
    const int row = tid >> 1;            // 0..127
    const int kq  = (tid & 1) * 4;       // 0 or 4
    const float* Xp = X + (long)(bm * 128 + row) * D + kq;
    const float* Wp = W + (long)(bn * 128 + row) * D + kq;
    const int ty = tid >> 4;             // 0..15 (rows)
    const int tx = tid & 15;             // 0..15 (cols)

    float acc[8][8];
#pragma unroll
    for (int i = 0; i < 8; i++)
#pragma unroll
        for (int j = 0; j < 8; j++) acc[i][j] = 0.f;

    for (int k0 = 0; k0 < D; k0 += 8) {
        float4 av = *(const float4*)(Xp + k0);
        float4 bv = *(const float4*)(Wp + k0);
        As[kq+0][row] = av.x; As[kq+1][row] = av.y;
        As[kq+2][row] = av.z; As[kq+3][row] = av.w;
        Bs[kq+0][row] = bv.x; Bs[kq+1][row] = bv.y;
        Bs[kq+2][row] = bv.z; Bs[kq+3][row] = bv.w;
        __syncthreads();
#pragma unroll
        for (int kk = 0; kk < 8; kk++) {
            float a[8], b0[4], b1[4];
#pragma unroll
            for (int i = 0; i < 8; i++) a[i] = As[kk][ty*8 + i];
#pragma unroll
            for (int j = 0; j < 4; j++) { b0[j] = Bs[kk][tx*4 + j]; b1[j] = Bs[kk][64 + tx*4 + j]; }
#pragma unroll
            for (int i = 0; i < 8; i++) {
#pragma unroll
                for (int j = 0; j < 4; j++) {
                    acc[i][j]     += a[i] * b0[j];
                    acc[i][4 + j] += a[i] * b1[j];
                }
            }
        }
        __syncthreads();
    }

    const int n0 = bn * 128 + tx * 4;
    const int n1 = n0 + 64;
    float bb0[4], bb1[4];
#pragma unroll
    for (int j = 0; j < 4; j++) { bb0[j] = bias[n0 + j]; bb1[j] = bias[n1 + j]; }

#pragma unroll
    for (int i = 0; i < 8; i++) {
        const int m = bm * 128 + ty * 8 + i;
        float4 v0 = make_float4(acc[i][0] + bb0[0], acc[i][1] + bb0[1],
                                acc[i][2] + bb0[2], acc[i][3] + bb0[3]);
        float4 v1 = make_float4(acc[i][4] + bb1[0], acc[i][5] + bb1[1],
                                acc[i][6] + bb1[2], acc[i][7] + bb1[3]);
        if (split) {
            const int b_ = m >> 11;          // m / S
            const int s_ = m & 2047;         // m % S
            const int h0 = n0 >> 6, dh0 = n0 & 63;
            const int h1 = n1 >> 6, dh1 = n1 & 63;
            *(float4*)(Y + ((long)(b_ * H + h0) * S + s_) * DH + dh0) = v0;
            *(float4*)(Y + ((long)(b_ * H + h1) * S + s_) * DH + dh1) = v1;
        } else {
            float* o = Y + (long)m * D;
            *(float4*)(o + n0) = v0;
            *(float4*)(o + n1) = v1;
        }
    }
}

// ---------------------------------------------------------------------------
// Scores: raw scaled scores[bh, q, k] = scale * Q[bh,q,:] . K[bh,k,:]
// 128x128 output tile, K-dim (DH=64) chunked by 32, 256 threads, 8x8 micro.
// ---------------------------------------------------------------------------
__global__ __launch_bounds__(256) void scores_kernel(
    const float* __restrict__ Q, const float* __restrict__ K,
    float* __restrict__ Wt)
{
    __shared__ float Qs[32][133];   // [k-in-chunk][q-row], padded
    __shared__ float Ks[32][133];   // [k-in-chunk][k-row]
    const int kt = blockIdx.x, qt = blockIdx.y, bh = blockIdx.z;
    const float* Qp = Q + ((long)bh * S + qt * 128) * DH;
    const float* Kp = K + ((long)bh * S + kt * 128) * DH;
    const int tid = threadIdx.x;
    const int ty = tid >> 4, tx = tid & 15;

    float acc[8][8];
#pragma unroll
    for (int i = 0; i < 8; i++)
#pragma unroll
        for (int j = 0; j < 8; j++) acc[i][j] = 0.f;

    for (int k0 = 0; k0 < DH; k0 += 32) {
#pragma unroll
        for (int t = 0; t < 4; t++) {
            const int idx = tid + t * 256;     // float4 index, 0..1023
            const int r = idx >> 3;            // 0..127
            const int c = (idx & 7) * 4;       // 0..28
            float4 qv = *(const float4*)(Qp + (long)r * DH + k0 + c);
            Qs[c+0][r] = qv.x; Qs[c+1][r] = qv.y; Qs[c+2][r] = qv.z; Qs[c+3][r] = qv.w;
            float4 kv = *(const float4*)(Kp + (long)r * DH + k0 + c);
            Ks[c+0][r] = kv.x; Ks[c+1][r] = kv.y; Ks[c+2][r] = kv.z; Ks[c+3][r] = kv.w;
        }
        __syncthreads();
#pragma unroll
        for (int kk = 0; kk < 32; kk++) {
            float a[8], b0[4], b1[4];
#pragma unroll
            for (int i = 0; i < 8; i++) a[i] = Qs[kk][ty*8 + i];
#pragma unroll
            for (int j = 0; j < 4; j++) { b0[j] = Ks[kk][tx*4 + j]; b1[j] = Ks[kk][64 + tx*4 + j]; }
#pragma unroll
            for (int i = 0; i < 8; i++) {
#pragma unroll
                for (int j = 0; j < 4; j++) {
                    acc[i][j]     += a[i] * b0[j];
                    acc[i][4 + j] += a[i] * b1[j];
                }
            }
        }
        __syncthreads();
    }

    const float scale = 0.125f;  // 1/sqrt(64)
    float* op = Wt + ((long)bh * S + qt * 128) * S + (long)kt * 128;
#pragma unroll
    for (int i = 0; i < 8; i++) {
        const int r = ty * 8 + i;
        float4 v0 = make_float4(acc[i][0]*scale, acc[i][1]*scale, acc[i][2]*scale, acc[i][3]*scale);
        float4 v1 = make_float4(acc[i][4]*scale, acc[i][5]*scale, acc[i][6]*scale, acc[i][7]*scale);
        *(float4*)(op + (long)r * S + tx * 4) = v0;
        *(float4*)(op + (long)r * S + 64 + tx * 4) = v1;
    }
}

// ---------------------------------------------------------------------------
// Row softmax in place (applies mask at read). One block per (bh, q) row.
// ---------------------------------------------------------------------------
__global__ __launch_bounds__(256) void softmax_kernel(
    float* __restrict__ Wt, const int* __restrict__ mask)
{
    const long row = blockIdx.x;          // 0 .. NBH*S-1
    const int bh = (int)(row >> 11);
    const int q  = (int)(row & 2047);
    const int b_ = bh >> 4;               // bh / H
    float* p = Wt + row * (long)S;
    const int* mrow = mask + ((long)b_ * S + q) * S;
    const int tid = threadIdx.x;

    float vals[8];
    float mx = -INFINITY;
#pragma unroll
    for (int t = 0; t < 8; t++) {
        const int k = tid + t * 256;
        float v = p[k];
        if (mrow[k] == 0) v = -INFINITY;
        vals[t] = v;
        mx = fmaxf(mx, v);
    }

    __shared__ float red[8];
#pragma unroll
    for (int o = 16; o > 0; o >>= 1)
        mx = fmaxf(mx, __shfl_xor_sync(0xffffffffu, mx, o));
    if ((tid & 31) == 0) red[tid >> 5] = mx;
    __syncthreads();
    mx = -INFINITY;
#pragma unroll
    for (int i = 0; i < 8; i++) mx = fmaxf(mx, red[i]);
    __syncthreads();

    float s = 0.f;
#pragma unroll
    for (int t = 0; t < 8; t++) {
        vals[t] = __expf(vals[t] - mx);
        s += vals[t];
    }
#pragma unroll
    for (int o = 16; o > 0; o >>= 1)
        s += __shfl_xor_sync(0xffffffffu, s, o);
    if ((tid & 31) == 0) red[tid >> 5] = s;
    __syncthreads();
    s = 0.f;
#pragma unroll
    for (int i = 0; i < 8; i++) s += red[i];
    const float inv = 1.f / s;

#pragma unroll
    for (int t = 0; t < 8; t++) {
        const int k = tid + t * 256;
        p[k] = vals[t] * inv;
    }
}

// ---------------------------------------------------------------------------
// PV: O[b, q, h*64+dh] = sum_k W[bh,q,k] * V[bh,k,dh]
// 128(q) x 64(dh) tile, BK=32, 128 threads, 8x8 micro (cols split 4+4).
// ---------------------------------------------------------------------------
__global__ __launch_bounds__(128) void pv_kernel(
    const float* __restrict__ Wt, const float* __restrict__ V,
    float* __restrict__ O)
{
    __shared__ float Ws[32][133];   // [k-in-chunk][q-row], padded
    __shared__ float Vs[32][64];    // [k-in-chunk][dh], natural
    const int qt = blockIdx.x, bh = blockIdx.y;
    const int b_ = bh >> 4, h = bh & 15;
    const float* Wp = Wt + ((long)bh * S + qt * 128) * S;
    const float* Vp = V + (long)bh * S * DH;
    const int tid = threadIdx.x;
    const int ty = tid >> 3;      // 0..15 (q groups of 8)
    const int tx = tid & 7;       // 0..7  (dh groups of 4, split 4+4)

    float acc[8][8];
#pragma unroll
    for (int i = 0; i < 8; i++)
#pragma unroll
        for (int j = 0; j < 8; j++) acc[i][j] = 0.f;

    for (int k0 = 0; k0 < S; k0 += 32) {
#pragma unroll
        for (int t = 0; t < 8; t++) {
            const int idx = tid + t * 128;   // 0..1023
            const int r = idx >> 3;          // 0..127
            const int c = (idx & 7) * 4;     // 0..28
            float4 wv = *(const float4*)(Wp + (long)r * S + k0 + c);
            Ws[c+0][r] = wv.x; Ws[c+1][r] = wv.y; Ws[c+2][r] = wv.z; Ws[c+3][r] = wv.w;
        }
#pragma unroll
        for (int t = 0; t < 4; t++) {
            const int idx = tid + t * 128;   // 0..511
            const int r = idx >> 4;          // 0..31
            const int c = (idx & 15) * 4;    // 0..60
            *(float4*)(&Vs[r][c]) = *(const float4*)(Vp + (long)(k0 + r) * DH + c);
        }
        __syncthreads();
#pragma unroll
        for (int kk = 0; kk < 32; kk++) {
            float a[8], b0[4], b1[4];
#pragma unroll
            for (int i = 0; i < 8; i++) a[i] = Ws[kk][ty*8 + i];
#pragma unroll
            for (int j = 0; j < 4; j++) { b0[j] = Vs[kk][tx*4 + j]; b1[j] = Vs[kk][32 + tx*4 + j]; }
#pragma unroll
            for (int i = 0; i < 8; i++) {
#pragma unroll
                for (int j = 0; j < 4; j++) {
                    acc[i][j]     += a[i] * b0[j];
                    acc[i][4 + j] += a[i] * b1[j];
                }
            }
        }
        __syncthreads();
    }

#pragma unroll
    for (int i = 0; i < 8; i++) {
        const int s_ = qt * 128 + ty * 8 + i;
        float* op = O + ((long)b_ * S + s_) * D + h * DH;
        float4 v0 = make_float4(acc[i][0], acc[i][1], acc[i][2], acc[i][3]);
        float4 v1 = make_float4(acc[i][4], acc[i][5], acc[i][6], acc[i][7]);
        *(float4*)(op + tx * 4) = v0;
        *(float4*)(op + 32 + tx * 4) = v1;
    }
}

// ---------------------------------------------------------------------------
extern "C" void kernel_launch(void* const* d_in, const int* in_sizes, int n_in,
                              void* d_out, int out_size)
{
    const float* q      = (const float*)d_in[0];
    const float* k      = (const float*)d_in[1];
    const float* v      = (const float*)d_in[2];
    const int*   mask   = (const int*)d_in[3];
    const float* wq_w   = (const float*)d_in[4];
    const float* wq_b   = (const float*)d_in[5];
    const float* wk_w   = (const float*)d_in[6];
    const float* wk_b   = (const float*)d_in[7];
    const float* wv_w   = (const float*)d_in[8];
    const float* wv_b   = (const float*)d_in[9];
    const float* dw     = (const float*)d_in[10];
    const float* db     = (const float*)d_in[11];

    float* out = (float*)d_out;             // [B,S,D]
    float* wts = out + OUT_ELEMS;           // [B,H,S,S]

    float *qp, *kp, *vp, *attn;
    cudaGetSymbolAddress((void**)&qp,   g_qp);
    cudaGetSymbolAddress((void**)&kp,   g_kp);
    cudaGetSymbolAddress((void**)&vp,   g_vp);
    cudaGetSymbolAddress((void**)&attn, g_attn);

    dim3 gProj(D / 128, MROWS / 128);       // (8, 32)
    sgemm_bias_kernel<<<gProj, 256>>>(q, wq_w, wq_b, qp, 1);
    sgemm_bias_kernel<<<gProj, 256>>>(k, wk_w, wk_b, kp, 1);
    sgemm_bias_kernel<<<gProj, 256>>>(v, wv_w, wv_b, vp, 1);

    scores_kernel<<<dim3(S / 128, S / 128, NBH), 256>>>(qp, kp, wts);
    softmax_kernel<<<NBH * S, 256>>>(wts, mask);
    pv_kernel<<<dim3(S / 128, NBH), 128>>>(wts, vp, attn);

    sgemm_bias_kernel<<<gProj, 256>>>(attn, dw, db, out, 0);
}

// round 2
// speedup vs baseline: 1.0058x; 1.0058x over previous
#include <cuda_runtime.h>
#include <math.h>

// Problem constants
constexpr int B = 2, S = 2048, D = 1024, H = 16, DH = 64;
constexpr int MROWS = B * S;          // 4096
constexpr int NBH = B * H;            // 32
constexpr long OUT_ELEMS = (long)B * S * D;   // 4,194,304

// Scratch (device globals -> no allocation)
__device__ float g_qp[NBH * S * DH];      // 16 MB, [bh][s][dh]
__device__ float g_kp[NBH * S * DH];
__device__ float g_vp[NBH * S * DH];
__device__ float g_attn[MROWS * D];       // 16 MB, [b][s][d]

// ---------------------------------------------------------------------------
// SGEMM with bias: Y = X @ W^T + b.  X:[M=4096,K=1024], W:[N=1024,K=1024].
// split=1 -> write split-head layout [B,H,S,DH]; split=0 -> [M,N] row-major.
// 128x128 tile, BK=8, 256 threads, 8x8 micro-tile (cols split 4+4 for LDS).
// ---------------------------------------------------------------------------
__global__ __launch_bounds__(256) void sgemm_bias_kernel(
    const float* __restrict__ X, const float* __restrict__ W,
    const float* __restrict__ bias, float* __restrict__ Y, int split)
{
    __shared__ float As[8][132];
    __shared__ float Bs[8][132];
    const int tid = threadIdx.x;
    const int bn = blockIdx.x, bm = blockIdx.y;
    const int row = tid >> 1;            // 0..127
    const int kq  = (tid & 1) * 4;       // 0 or 4
    const float* Xp = X + (long)(bm * 128 + row) * D + kq;
    const float* Wp = W + (long)(bn * 128 + row) * D + kq;
    const int ty = tid >> 4;             // 0..15 (rows)
    const int tx = tid & 15;             // 0..15 (cols)

    float acc[8][8];
#pragma unroll
    for (int i = 0; i < 8; i++)
#pragma unroll
        for (int j = 0; j < 8; j++) acc[i][j] = 0.f;

    for (int k0 = 0; k0 < D; k0 += 8) {
        float4 av = *(const float4*)(Xp + k0);
        float4 bv = *(const float4*)(Wp + k0);
        As[kq+0][row] = av.x; As[kq+1][row] = av.y;
        As[kq+2][row] = av.z; As[kq+3][row] = av.w;
        Bs[kq+0][row] = bv.x; Bs[kq+1][row] = bv.y;
        Bs[kq+2][row] = bv.z; Bs[kq+3][row] = bv.w;
        __syncthreads();
#pragma unroll
        for (int kk = 0; kk < 8; kk++) {
            float a[8], b0[4], b1[4];
#pragma unroll
            for (int i = 0; i < 8; i++) a[i] = As[kk][ty*8 + i];
#pragma unroll
            for (int j = 0; j < 4; j++) { b0[j] = Bs[kk][tx*4 + j]; b1[j] = Bs[kk][64 + tx*4 + j]; }
#pragma unroll
            for (int i = 0; i < 8; i++) {
#pragma unroll
                for (int j = 0; j < 4; j++) {
                    acc[i][j]     += a[i] * b0[j];
                    acc[i][4 + j] += a[i] * b1[j];
                }
            }
        }
        __syncthreads();
    }

    const int n0 = bn * 128 + tx * 4;
    const int n1 = n0 + 64;
    float bb0[4], bb1[4];
#pragma unroll
    for (int j = 0; j < 4; j++) { bb0[j] = bias[n0 + j]; bb1[j] = bias[n1 + j]; }

#pragma unroll
    for (int i = 0; i < 8; i++) {
        const int m = bm * 128 + ty * 8 + i;
        float4 v0 = make_float4(acc[i][0] + bb0[0], acc[i][1] + bb0[1],
                                acc[i][2] + bb0[2], acc[i][3] + bb0[3]);
        float4 v1 = make_float4(acc[i][4] + bb1[0], acc[i][5] + bb1[1],
                                acc[i][6] + bb1[2], acc[i][7] + bb1[3]);
        if (split) {
            const int b_ = m >> 11;          // m / S
            const int s_ = m & 2047;         // m % S
            const int h0 = n0 >> 6, dh0 = n0 & 63;
            const int h1 = n1 >> 6, dh1 = n1 & 63;
            *(float4*)(Y + ((long)(b_ * H + h0) * S + s_) * DH + dh0) = v0;
            *(float4*)(Y + ((long)(b_ * H + h1) * S + s_) * DH + dh1) = v1;
        } else {
            float* o = Y + (long)m * D;
            *(float4*)(o + n0) = v0;
            *(float4*)(o + n1) = v1;
        }
    }
}

// ---------------------------------------------------------------------------
// Scores: raw scaled scores[bh, q, k] = scale * Q[bh,q,:] . K[bh,k,:]
// 128x128 output tile, K-dim (DH=64) chunked by 32, 256 threads, 8x8 micro.
// ---------------------------------------------------------------------------
__global__ __launch_bounds__(256) void scores_kernel(
    const float* __restrict__ Q, const float* __restrict__ K,
    float* __restrict__ Wt)
{
    __shared__ float Qs[32][133];   // [k-in-chunk][q-row], padded
    __shared__ float Ks[32][133];   // [k-in-chunk][k-row]
    const int kt = blockIdx.x, qt = blockIdx.y, bh = blockIdx.z;
    const float* Qp = Q + ((long)bh * S + qt * 128) * DH;
    const float* Kp = K + ((long)bh * S + kt * 128) * DH;
    const int tid = threadIdx.x;
    const int ty = tid >> 4, tx = tid & 15;

    float acc[8][8];
#pragma unroll
    for (int i = 0; i < 8; i++)
#pragma unroll
        for (int j = 0; j < 8; j++) acc[i][j] = 0.f;

    for (int k0 = 0; k0 < DH; k0 += 32) {
#pragma unroll
        for (int t = 0; t < 4; t++) {
            const int idx = tid + t * 256;     // float4 index, 0..1023
            const int r = idx >> 3;            // 0..127
            const int c = (idx & 7) * 4;       // 0..28
            float4 qv = *(const float4*)(Qp + (long)r * DH + k0 + c);
            Qs[c+0][r] = qv.x; Qs[c+1][r] = qv.y; Qs[c+2][r] = qv.z; Qs[c+3][r] = qv.w;
            float4 kv = *(const float4*)(Kp + (long)r * DH + k0 + c);
            Ks[c+0][r] = kv.x; Ks[c+1][r] = kv.y; Ks[c+2][r] = kv.z; Ks[c+3][r] = kv.w;
        }
        __syncthreads();
#pragma unroll
        for (int kk = 0; kk < 32; kk++) {
            float a[8], b0[4], b1[4];
#pragma unroll
            for (int i = 0; i < 8; i++) a[i] = Qs[kk][ty*8 + i];
#pragma unroll
            for (int j = 0; j < 4; j++) { b0[j] = Ks[kk][tx*4 + j]; b1[j] = Ks[kk][64 + tx*4 + j]; }
#pragma unroll
            for (int i = 0; i < 8; i++) {
#pragma unroll
                for (int j = 0; j < 4; j++) {
                    acc[i][j]     += a[i] * b0[j];
                    acc[i][4 + j] += a[i] * b1[j];
                }
            }
        }
        __syncthreads();
    }

    const float scale = 0.125f;  // 1/sqrt(64)
    float* op = Wt + ((long)bh * S + qt * 128) * S + (long)kt * 128;
#pragma unroll
    for (int i = 0; i < 8; i++) {
        const int r = ty * 8 + i;
        float4 v0 = make_float4(acc[i][0]*scale, acc[i][1]*scale, acc[i][2]*scale, acc[i][3]*scale);
        float4 v1 = make_float4(acc[i][4]*scale, acc[i][5]*scale, acc[i][6]*scale, acc[i][7]*scale);
        *(float4*)(op + (long)r * S + tx * 4) = v0;
        *(float4*)(op + (long)r * S + 64 + tx * 4) = v1;
    }
}

// ---------------------------------------------------------------------------
// Row softmax in place (applies mask at read). One block per (bh, q) row.
// ---------------------------------------------------------------------------
__global__ __launch_bounds__(256) void softmax_kernel(
    float* __restrict__ Wt, const int* __restrict__ mask)
{
    const long row = blockIdx.x;          // 0 .. NBH*S-1
    const int bh = (int)(row >> 11);
    const int q  = (int)(row & 2047);
    const int b_ = bh >> 4;               // bh / H
    float* p = Wt + row * (long)S;
    const int* mrow = mask + ((long)b_ * S + q) * S;
    const int tid = threadIdx.x;

    float vals[8];
    float mx = -INFINITY;
#pragma unroll
    for (int t = 0; t < 8; t++) {
        const int k = tid + t * 256;
        float v = p[k];
        if (mrow[k] == 0) v = -INFINITY;
        vals[t] = v;
        mx = fmaxf(mx, v);
    }

    __shared__ float red[8];
#pragma unroll
    for (int o = 16; o > 0; o >>= 1)
        mx = fmaxf(mx, __shfl_xor_sync(0xffffffffu, mx, o));
    if ((tid & 31) == 0) red[tid >> 5] = mx;
    __syncthreads();
    mx = -INFINITY;
#pragma unroll
    for (int i = 0; i < 8; i++) mx = fmaxf(mx, red[i]);
    __syncthreads();

    float s = 0.f;
#pragma unroll
    for (int t = 0; t < 8; t++) {
        vals[t] = __expf(vals[t] - mx);
        s += vals[t];
    }
#pragma unroll
    for (int o = 16; o > 0; o >>= 1)
        s += __shfl_xor_sync(0xffffffffu, s, o);
    if ((tid & 31) == 0) red[tid >> 5] = s;
    __syncthreads();
    s = 0.f;
#pragma unroll
    for (int i = 0; i < 8; i++) s += red[i];
    const float inv = 1.f / s;

#pragma unroll
    for (int t = 0; t < 8; t++) {
        const int k = tid + t * 256;
        p[k] = vals[t] * inv;
    }
}

// ---------------------------------------------------------------------------
// PV: O[b, q, h*64+dh] = sum_k W[bh,q,k] * V[bh,k,dh]
// 128(q) x 64(dh) tile, BK=32, 128 threads, 8x8 micro (cols split 4+4).
// ---------------------------------------------------------------------------
__global__ __launch_bounds__(128) void pv_kernel(
    const float* __restrict__ Wt, const float* __restrict__ V,
    float* __restrict__ O)
{
    __shared__ float Ws[32][133];   // [k-in-chunk][q-row], padded
    __shared__ float Vs[32][64];    // [k-in-chunk][dh], natural
    const int qt = blockIdx.x, bh = blockIdx.y;
    const int b_ = bh >> 4, h = bh & 15;
    const float* Wp = Wt + ((long)bh * S + qt * 128) * S;
    const float* Vp = V + (long)bh * S * DH;
    const int tid = threadIdx.x;
    const int ty = tid >> 3;      // 0..15 (q groups of 8)
    const int tx = tid & 7;       // 0..7  (dh groups of 4, split 4+4)

    float acc[8][8];
#pragma unroll
    for (int i = 0; i < 8; i++)
#pragma unroll
        for (int j = 0; j < 8; j++) acc[i][j] = 0.f;

    for (int k0 = 0; k0 < S; k0 += 32) {
#pragma unroll
        for (int t = 0; t < 8; t++) {
            const int idx = tid + t * 128;   // 0..1023
            const int r = idx >> 3;          // 0..127
            const int c = (idx & 7) * 4;     // 0..28
            float4 wv = *(const float4*)(Wp + (long)r * S + k0 + c);
            Ws[c+0][r] = wv.x; Ws[c+1][r] = wv.y; Ws[c+2][r] = wv.z; Ws[c+3][r] = wv.w;
        }
#pragma unroll
        for (int t = 0; t < 4; t++) {
            const int idx = tid + t * 128;   // 0..511
            const int r = idx >> 4;          // 0..31
            const int c = (idx & 15) * 4;    // 0..60
            *(float4*)(&Vs[r][c]) = *(const float4*)(Vp + (long)(k0 + r) * DH + c);
        }
        __syncthreads();
#pragma unroll
        for (int kk = 0; kk < 32; kk++) {
            float a[8], b0[4], b1[4];
#pragma unroll
            for (int i = 0; i < 8; i++) a[i] = Ws[kk][ty*8 + i];
#pragma unroll
            for (int j = 0; j < 4; j++) { b0[j] = Vs[kk][tx*4 + j]; b1[j] = Vs[kk][32 + tx*4 + j]; }
#pragma unroll
            for (int i = 0; i < 8; i++) {
#pragma unroll
                for (int j = 0; j < 4; j++) {
                    acc[i][j]     += a[i] * b0[j];
                    acc[i][4 + j] += a[i] * b1[j];
                }
            }
        }
        __syncthreads();
    }

#pragma unroll
    for (int i = 0; i < 8; i++) {
        const int s_ = qt * 128 + ty * 8 + i;
        float* op = O + ((long)b_ * S + s_) * D + h * DH;
        float4 v0 = make_float4(acc[i][0], acc[i][1], acc[i][2], acc[i][3]);
        float4 v1 = make_float4(acc[i][4], acc[i][5], acc[i][6], acc[i][7]);
        *(float4*)(op + tx * 4) = v0;
        *(float4*)(op + 32 + tx * 4) = v1;
    }
}

// ---------------------------------------------------------------------------
extern "C" void kernel_launch(void* const* d_in, const int* in_sizes, int n_in,
                              void* d_out, int out_size)
{
    const float* q      = (const float*)d_in[0];
    const float* k      = (const float*)d_in[1];
    const float* v      = (const float*)d_in[2];
    const int*   mask   = (const int*)d_in[3];
    const float* wq_w   = (const float*)d_in[4];
    const float* wq_b   = (const float*)d_in[5];
    const float* wk_w   = (const float*)d_in[6];
    const float* wk_b   = (const float*)d_in[7];
    const float* wv_w   = (const float*)d_in[8];
    const float* wv_b   = (const float*)d_in[9];
    const float* dw     = (const float*)d_in[10];
    const float* db     = (const float*)d_in[11];

    float* out = (float*)d_out;             // [B,S,D]
    float* wts = out + OUT_ELEMS;           // [B,H,S,S]

    float *qp, *kp, *vp, *attn;
    cudaGetSymbolAddress((void**)&qp,   g_qp);
    cudaGetSymbolAddress((void**)&kp,   g_kp);
    cudaGetSymbolAddress((void**)&vp,   g_vp);
    cudaGetSymbolAddress((void**)&attn, g_attn);

    dim3 gProj(D / 128, MROWS / 128);       // (8, 32)
    sgemm_bias_kernel<<<gProj, 256>>>(q, wq_w, wq_b, qp, 1);
    sgemm_bias_kernel<<<gProj, 256>>>(k, wk_w, wk_b, kp, 1);
    sgemm_bias_kernel<<<gProj, 256>>>(v, wv_w, wv_b, vp, 1);

    scores_kernel<<<dim3(S / 128, S / 128, NBH), 256>>>(qp, kp, wts);
    softmax_kernel<<<NBH * S, 256>>>(wts, mask);
    pv_kernel<<<dim3(S / 128, NBH), 128>>>(wts, vp, attn);

    sgemm_bias_kernel<<<gProj, 256>>>(attn, dw, db, out, 0);
}

// round 4
// speedup vs baseline: 1.7673x; 1.7570x over previous
#include <cuda_runtime.h>
#include <cuda_bf16.h>
#include <stdint.h>
#include <math.h>

typedef __nv_bfloat16 bf16;

constexpr long OUT_ELEMS = 4194304L;   // B*S*D

// ---------------- scratch: device globals (no allocation) ----------------
__device__ __align__(256) bf16 g_xq_hi[4194304], g_xq_lo[4194304];
__device__ __align__(256) bf16 g_xk_hi[4194304], g_xk_lo[4194304];
__device__ __align__(256) bf16 g_xv_hi[4194304], g_xv_lo[4194304];
__device__ __align__(256) bf16 g_wq_hi[1048576], g_wq_lo[1048576];
__device__ __align__(256) bf16 g_wk_hi[1048576], g_wk_lo[1048576];
__device__ __align__(256) bf16 g_wv_hi[1048576], g_wv_lo[1048576];
__device__ __align__(256) bf16 g_wd_hi[1048576], g_wd_lo[1048576];
__device__ __align__(256) bf16 g_qp_hi[4194304], g_qp_lo[4194304];  // [bh][s][64]
__device__ __align__(256) bf16 g_kp_hi[4194304], g_kp_lo[4194304];  // [bh][s][64]
__device__ __align__(256) bf16 g_vp_hi[4194304], g_vp_lo[4194304];  // [bh][s][64]
__device__ __align__(256) float g_attn[4194304];                    // [b*S+s][1024]
__device__ __align__(256) bf16 g_ah[4194304], g_al[4194304];

// ---------------- helpers ----------------
__device__ __forceinline__ uint32_t smem_u32(const void* p) {
    uint32_t a;
    asm("{ .reg .u64 t; cvta.to.shared.u64 t, %1; cvt.u32.u64 %0, t; }" : "=r"(a) : "l"(p));
    return a;
}
__device__ __forceinline__ void cpa16(uint32_t d, const void* g) {
    asm volatile("cp.async.cg.shared.global [%0], [%1], 16;" :: "r"(d), "l"(g));
}
#define CP_COMMIT() asm volatile("cp.async.commit_group;" ::: "memory")
#define CP_WAIT0()  asm volatile("cp.async.wait_group 0;" ::: "memory")
#define CP_WAIT1()  asm volatile("cp.async.wait_group 1;" ::: "memory")

__device__ __forceinline__ void ldm_x4(uint32_t& r0, uint32_t& r1, uint32_t& r2, uint32_t& r3, uint32_t a) {
    asm volatile("ldmatrix.sync.aligned.m8n8.x4.shared.b16 {%0,%1,%2,%3}, [%4];"
                 : "=r"(r0), "=r"(r1), "=r"(r2), "=r"(r3) : "r"(a));
}
__device__ __forceinline__ void ldm_x4t(uint32_t& r0, uint32_t& r1, uint32_t& r2, uint32_t& r3, uint32_t a) {
    asm volatile("ldmatrix.sync.aligned.m8n8.x4.trans.shared.b16 {%0,%1,%2,%3}, [%4];"
                 : "=r"(r0), "=r"(r1), "=r"(r2), "=r"(r3) : "r"(a));
}
__device__ __forceinline__ void mma16816(float* c, const uint32_t* a, const uint32_t* b) {
    asm volatile(
        "mma.sync.aligned.m16n8k16.row.col.f32.bf16.bf16.f32 "
        "{%0,%1,%2,%3}, {%4,%5,%6,%7}, {%8,%9}, {%0,%1,%2,%3};"
        : "+f"(c[0]), "+f"(c[1]), "+f"(c[2]), "+f"(c[3])
        : "r"(a[0]), "r"(a[1]), "r"(a[2]), "r"(a[3]), "r"(b[0]), "r"(b[1]));
}

__device__ __forceinline__ uint32_t pack2(bf16 a, bf16 b) {
    return (uint32_t)__bfloat16_as_ushort(a) | ((uint32_t)__bfloat16_as_ushort(b) << 16);
}
__device__ __forceinline__ void split1(float v, bf16& h, bf16& l) {
    h = __float2bfloat16_rn(v);
    l = __float2bfloat16_rn(v - __bfloat162float(h));
}

// --------------- warp-tile GEMM core (3-term compensated) ---------------
template<int MT, int NT, int NK, bool TRB>
__device__ __forceinline__ void gemm_pass(float (&acc)[MT][NT][4],
        uint32_t ab, uint32_t bb, int astr, int bstr, int lane)
{
    const int a_row = (lane & 7) + ((lane >> 3) & 1) * 8;
    const int a_k16 = (lane >> 4) * 16;
    const int b_row = (lane & 7) + (lane >> 4) * 8;
    const int b_k16 = ((lane >> 3) & 1) * 16;
    const int bt_row = (lane & 7) + ((lane >> 3) & 1) * 8;
    const int bt_col = (lane >> 4) * 8;
#pragma unroll
    for (int ks = 0; ks < NK; ks++) {
        uint32_t af[MT][4];
#pragma unroll
        for (int mt = 0; mt < MT; mt++)
            ldm_x4(af[mt][0], af[mt][1], af[mt][2], af[mt][3],
                   ab + (mt * 16 + a_row) * astr + ks * 32 + a_k16);
        uint32_t bfr[NT][2];
#pragma unroll
        for (int np = 0; np < NT / 2; np++) {
            uint32_t r0, r1, r2, r3;
            if (TRB)
                ldm_x4t(r0, r1, r2, r3, bb + (ks * 16 + bt_row) * bstr + (np * 16 + bt_col) * 2);
            else
                ldm_x4(r0, r1, r2, r3, bb + (np * 16 + b_row) * bstr + ks * 32 + b_k16);
            bfr[2*np][0] = r0; bfr[2*np][1] = r1;
            bfr[2*np+1][0] = r2; bfr[2*np+1][1] = r3;
        }
#pragma unroll
        for (int mt = 0; mt < MT; mt++)
#pragma unroll
            for (int nt = 0; nt < NT; nt++)
                mma16816(acc[mt][nt], af[mt], bfr[nt]);
    }
}

template<int MT, int NT, int NK, bool TRB>
__device__ __forceinline__ void gemm3(float (&acc)[MT][NT][4],
        uint32_t ahi, uint32_t alo, uint32_t bhi, uint32_t blo,
        int astr, int bstr, int lane)
{
    gemm_pass<MT, NT, NK, TRB>(acc, ahi, bhi, astr, bstr, lane);
    gemm_pass<MT, NT, NK, TRB>(acc, ahi, blo, astr, bstr, lane);
    gemm_pass<MT, NT, NK, TRB>(acc, alo, bhi, astr, bstr, lane);
}

// ---------------- split: fp32 -> hi/lo bf16 ----------------
__global__ void split_kernel(const float* __restrict__ x, bf16* __restrict__ hi,
                             bf16* __restrict__ lo, int n4) {
    for (long i = blockIdx.x * blockDim.x + threadIdx.x; i < n4; i += (long)gridDim.x * blockDim.x) {
        float4 v = *(const float4*)(x + i * 4);
        bf16 h0, l0, h1, l1, h2, l2, h3, l3;
        split1(v.x, h0, l0); split1(v.y, h1, l1);
        split1(v.z, h2, l2); split1(v.w, h3, l3);
        *(uint2*)(hi + i * 4) = make_uint2(pack2(h0, h1), pack2(h2, h3));
        *(uint2*)(lo + i * 4) = make_uint2(pack2(l0, l1), pack2(l2, l3));
    }
}

// ---------------- proj GEMM: Y = X @ W^T + b ----------------
// Block 128x128, 8 warps (2x4), BK=32, double-buffered cp.async.
// mode 0: write split-head bf16 hi/lo [bh][s][64]; mode 2: fp32 dense [m][1024]
// smem: 2 buffers x 4 tiles x (128 x 40 bf16 = 10240 B) = 81920 B
__global__ __launch_bounds__(256) void proj_kernel(
    const bf16* __restrict__ Ahi, const bf16* __restrict__ Alo,
    const bf16* __restrict__ Bhi, const bf16* __restrict__ Blo,
    const float* __restrict__ bias, float* __restrict__ outD,
    bf16* __restrict__ Phi, bf16* __restrict__ Plo, int mode)
{
    extern __shared__ char smem[];
    const uint32_t sb = smem_u32(smem);
    const int tid = threadIdx.x, lane = tid & 31, wid = tid >> 5;
    const int warp_m = wid >> 2, warp_n = wid & 3;
    const long m0 = (long)blockIdx.y * 128, n0 = (long)blockIdx.x * 128;

    float acc[4][4][4];
#pragma unroll
    for (int i = 0; i < 4; i++)
#pragma unroll
        for (int j = 0; j < 4; j++)
#pragma unroll
            for (int k = 0; k < 4; k++) acc[i][j][k] = 0.f;

    const bf16* srcA[2] = {Ahi + m0 * 1024, Alo + m0 * 1024};
    const bf16* srcB[2] = {Bhi + n0 * 1024, Blo + n0 * 1024};

    auto load_chunk = [&](int buf, int kb) {
        uint32_t base = sb + buf * 40960;
#pragma unroll
        for (int t = 0; t < 4; t++) {
            const bf16* s = (t < 2 ? srcA[t] : srcB[t - 2]) + kb;
            uint32_t db = base + t * 10240;
#pragma unroll
            for (int j = 0; j < 2; j++) {
                int idx = tid + j * 256;
                int r = idx >> 2, c = idx & 3;
                cpa16(db + r * 80 + c * 16, s + (long)r * 1024 + c * 8);
            }
        }
    };

    load_chunk(0, 0);
    CP_COMMIT();
    const int aoff = warp_m * 64 * 80, boff = warp_n * 32 * 80;
    for (int ch = 0; ch < 32; ch++) {
        if (ch < 31) { load_chunk((ch + 1) & 1, (ch + 1) * 32); CP_COMMIT(); CP_WAIT1(); }
        else CP_WAIT0();
        __syncthreads();
        uint32_t b = sb + (ch & 1) * 40960;
        gemm3<4, 4, 2, false>(acc, b + aoff, b + 10240 + aoff,
                              b + 20480 + boff, b + 30720 + boff, 80, 80, lane);
        __syncthreads();
    }

    // epilogue
#pragma unroll
    for (int mt = 0; mt < 4; mt++) {
#pragma unroll
        for (int nt = 0; nt < 4; nt++) {
            int n = (int)n0 + warp_n * 32 + nt * 8 + (lane & 3) * 2;
            float bv0 = bias[n], bv1 = bias[n + 1];
            long r0 = m0 + warp_m * 64 + mt * 16 + (lane >> 2);
            long r1 = r0 + 8;
            float v00 = acc[mt][nt][0] + bv0, v01 = acc[mt][nt][1] + bv1;
            float v10 = acc[mt][nt][2] + bv0, v11 = acc[mt][nt][3] + bv1;
            if (mode == 2) {
                *(float2*)(outD + r0 * 1024 + n) = make_float2(v00, v01);
                *(float2*)(outD + r1 * 1024 + n) = make_float2(v10, v11);
            } else {
                int h = n >> 6, dh = n & 63;
                {
                    int b_ = (int)(r0 >> 11), s_ = (int)(r0 & 2047);
                    long a = ((long)(b_ * 16 + h) * 2048 + s_) * 64 + dh;
                    bf16 hh0, ll0, hh1, ll1;
                    split1(v00, hh0, ll0); split1(v01, hh1, ll1);
                    *(uint32_t*)(Phi + a) = pack2(hh0, hh1);
                    *(uint32_t*)(Plo + a) = pack2(ll0, ll1);
                }
                {
                    int b_ = (int)(r1 >> 11), s_ = (int)(r1 & 2047);
                    long a = ((long)(b_ * 16 + h) * 2048 + s_) * 64 + dh;
                    bf16 hh0, ll0, hh1, ll1;
                    split1(v10, hh0, ll0); split1(v11, hh1, ll1);
                    *(uint32_t*)(Phi + a) = pack2(hh0, hh1);
                    *(uint32_t*)(Plo + a) = pack2(ll0, ll1);
                }
            }
        }
    }
}

// ---------------- scores: Wt[bh,q,k] = 0.125 * Q . K ----------------
// Block 128(q) x 128(k), 8 warps (2x4), K=64 single shot.
// smem: 4 tiles x (128 x 72 bf16 = 18432 B) = 73728 B
__global__ __launch_bounds__(256) void scores_kernel(
    const bf16* __restrict__ Qhi, const bf16* __restrict__ Qlo,
    const bf16* __restrict__ Khi, const bf16* __restrict__ Klo,
    float* __restrict__ Wt)
{
    extern __shared__ char smem[];
    const uint32_t sb = smem_u32(smem);
    const int tid = threadIdx.x, lane = tid & 31, wid = tid >> 5;
    const int warp_m = wid >> 2, warp_n = wid & 3;
    const int kt = blockIdx.x, qt = blockIdx.y, bh = blockIdx.z;

    const bf16* srcs[4] = {
        Qhi + ((long)bh * 2048 + qt * 128) * 64,
        Qlo + ((long)bh * 2048 + qt * 128) * 64,
        Khi + ((long)bh * 2048 + kt * 128) * 64,
        Klo + ((long)bh * 2048 + kt * 128) * 64};
#pragma unroll
    for (int t = 0; t < 4; t++) {
        uint32_t db = sb + t * 18432;
#pragma unroll
        for (int j = 0; j < 4; j++) {
            int idx = tid + j * 256;
            int r = idx >> 3, c = idx & 7;
            cpa16(db + r * 144 + c * 16, srcs[t] + (long)r * 64 + c * 8);
        }
    }
    CP_COMMIT(); CP_WAIT0();
    __syncthreads();

    float acc[4][4][4];
#pragma unroll
    for (int i = 0; i < 4; i++)
#pragma unroll
        for (int j = 0; j < 4; j++)
#pragma unroll
            for (int k = 0; k < 4; k++) acc[i][j][k] = 0.f;

    const int aoff = warp_m * 64 * 144, boff = warp_n * 32 * 144;
    gemm3<4, 4, 4, false>(acc, sb + aoff, sb + 18432 + aoff,
                          sb + 36864 + boff, sb + 55296 + boff, 144, 144, lane);

    float* base = Wt + ((long)bh * 2048 + qt * 128) * 2048 + kt * 128;
#pragma unroll
    for (int mt = 0; mt < 4; mt++) {
#pragma unroll
        for (int nt = 0; nt < 4; nt++) {
            int r0 = warp_m * 64 + mt * 16 + (lane >> 2);
            int c = warp_n * 32 + nt * 8 + (lane & 3) * 2;
            *(float2*)(base + (long)r0 * 2048 + c) =
                make_float2(acc[mt][nt][0] * 0.125f, acc[mt][nt][1] * 0.125f);
            *(float2*)(base + (long)(r0 + 8) * 2048 + c) =
                make_float2(acc[mt][nt][2] * 0.125f, acc[mt][nt][3] * 0.125f);
        }
    }
}

// ---------------- softmax (in place, mask at read) ----------------
__global__ __launch_bounds__(256) void softmax_kernel(
    float* __restrict__ Wt, const int* __restrict__ mask)
{
    const long row = blockIdx.x;
    const int bh = (int)(row >> 11), q = (int)(row & 2047), b_ = bh >> 4;
    float* p = Wt + row * 2048L;
    const int* mrow = mask + ((long)b_ * 2048 + q) * 2048;
    const int tid = threadIdx.x;

    float vals[8];
    float mx = -INFINITY;
#pragma unroll
    for (int t = 0; t < 8; t++) {
        const int k = tid + t * 256;
        float v = p[k];
        if (mrow[k] == 0) v = -INFINITY;
        vals[t] = v;
        mx = fmaxf(mx, v);
    }
    __shared__ float red[8];
#pragma unroll
    for (int o = 16; o > 0; o >>= 1) mx = fmaxf(mx, __shfl_xor_sync(0xffffffffu, mx, o));
    if ((tid & 31) == 0) red[tid >> 5] = mx;
    __syncthreads();
    mx = -INFINITY;
#pragma unroll
    for (int i = 0; i < 8; i++) mx = fmaxf(mx, red[i]);
    __syncthreads();
    float s = 0.f;
#pragma unroll
    for (int t = 0; t < 8; t++) { vals[t] = __expf(vals[t] - mx); s += vals[t]; }
#pragma unroll
    for (int o = 16; o > 0; o >>= 1) s += __shfl_xor_sync(0xffffffffu, s, o);
    if ((tid & 31) == 0) red[tid >> 5] = s;
    __syncthreads();
    s = 0.f;
#pragma unroll
    for (int i = 0; i < 8; i++) s += red[i];
    const float inv = 1.f / s;
#pragma unroll
    for (int t = 0; t < 8; t++) p[tid + t * 256] = vals[t] * inv;
}

// ---------------- PV: O = W @ V ----------------
// Block 128(q) x 64(dh), 8 warps (4x2), BK=32 over K=2048, double-buffered.
// W fp32 from gmem, split to hi/lo bf16 in smem; V bf16 [s][64] via ldmatrix.trans.
// smem: raw 2x18432, vh 2x4608, vl 2x4608, wh 10240, wl 10240 = 75776 B
__global__ __launch_bounds__(256) void pv_kernel(
    const float* __restrict__ Wt, const bf16* __restrict__ Vhi,
    const bf16* __restrict__ Vlo, float* __restrict__ O)
{
    extern __shared__ char smem[];
    const uint32_t sb = smem_u32(smem);
    const int tid = threadIdx.x, lane = tid & 31, wid = tid >> 5;
    const int warp_m = wid >> 1, warp_n = wid & 1;
    const int qt = blockIdx.x, bh = blockIdx.y;
    const uint32_t RAW0 = 0, RAW1 = 18432, VH0 = 36864, VH1 = 41472,
                   VL0 = 46080, VL1 = 50688, WH = 55296, WL = 65536;

    const float* wsrc = Wt + ((long)bh * 2048 + qt * 128) * 2048;
    const bf16* vhsrc = Vhi + (long)bh * 2048 * 64;
    const bf16* vlsrc = Vlo + (long)bh * 2048 * 64;

    auto load_chunk = [&](int buf, int ch) {
        uint32_t raw = sb + (buf ? RAW1 : RAW0);
        uint32_t vh = sb + (buf ? VH1 : VH0);
        uint32_t vl = sb + (buf ? VL1 : VL0);
        const float* wp = wsrc + ch * 32;
#pragma unroll
        for (int j = 0; j < 4; j++) {
            int idx = tid + j * 256;
            int r = idx >> 3, c = idx & 7;
            cpa16(raw + r * 144 + c * 16, wp + (long)r * 2048 + c * 4);
        }
        {
            int r = tid >> 3, c = tid & 7;
            cpa16(vh + r * 144 + c * 16, vhsrc + (long)(ch * 32 + r) * 64 + c * 8);
            cpa16(vl + r * 144 + c * 16, vlsrc + (long)(ch * 32 + r) * 64 + c * 8);
        }
    };

    float acc[2][4][4];
#pragma unroll
    for (int i = 0; i < 2; i++)
#pragma unroll
        for (int j = 0; j < 4; j++)
#pragma unroll
            for (int k = 0; k < 4; k++) acc[i][j][k] = 0.f;

    load_chunk(0, 0);
    CP_COMMIT();
    const int crow = tid >> 1, chalf = tid & 1;
    const int aoff = warp_m * 32 * 80, boff = warp_n * 32 * 2;
    for (int ch = 0; ch < 64; ch++) {
        if (ch < 63) { load_chunk((ch + 1) & 1, ch + 1); CP_COMMIT(); CP_WAIT1(); }
        else CP_WAIT0();
        __syncthreads();
        // convert raw fp32 -> WH/WL padded bf16
        {
            const char* rp = smem + (ch & 1 ? RAW1 : RAW0) + crow * 144 + chalf * 64;
            uint32_t uh[8], ul[8];
#pragma unroll
            for (int i = 0; i < 4; i++) {
                float4 v = *(const float4*)(rp + i * 16);
                bf16 h0, l0, h1, l1;
                split1(v.x, h0, l0); split1(v.y, h1, l1);
                uh[i * 2] = pack2(h0, h1); ul[i * 2] = pack2(l0, l1);
                split1(v.z, h0, l0); split1(v.w, h1, l1);
                uh[i * 2 + 1] = pack2(h0, h1); ul[i * 2 + 1] = pack2(l0, l1);
            }
            char* wh = smem + WH + crow * 80 + chalf * 32;
            char* wl = smem + WL + crow * 80 + chalf * 32;
            *(uint4*)wh = make_uint4(uh[0], uh[1], uh[2], uh[3]);
            *(uint4*)(wh + 16) = make_uint4(uh[4], uh[5], uh[6], uh[7]);
            *(uint4*)wl = make_uint4(ul[0], ul[1], ul[2], ul[3]);
            *(uint4*)(wl + 16) = make_uint4(ul[4], ul[5], ul[6], ul[7]);
        }
        __syncthreads();
        uint32_t vh = sb + ((ch & 1) ? VH1 : VH0) + boff;
        uint32_t vl = sb + ((ch & 1) ? VL1 : VL0) + boff;
        gemm3<2, 4, 2, true>(acc, sb + WH + aoff, sb + WL + aoff, vh, vl, 80, 144, lane);
        __syncthreads();
    }

    const int b_ = bh >> 4, h = bh & 15;
#pragma unroll
    for (int mt = 0; mt < 2; mt++) {
#pragma unroll
        for (int nt = 0; nt < 4; nt++) {
            int s0 = qt * 128 + warp_m * 32 + mt * 16 + (lane >> 2);
            int dh = warp_n * 32 + nt * 8 + (lane & 3) * 2;
            float* p0 = O + ((long)b_ * 2048 + s0) * 1024 + h * 64 + dh;
            *(float2*)p0 = make_float2(acc[mt][nt][0], acc[mt][nt][1]);
            *(float2*)(p0 + 8 * 1024) = make_float2(acc[mt][nt][2], acc[mt][nt][3]);
        }
    }
}

// ---------------- host launcher ----------------
extern "C" void kernel_launch(void* const* d_in, const int* in_sizes, int n_in,
                              void* d_out, int out_size)
{
    const float* q    = (const float*)d_in[0];
    const float* k    = (const float*)d_in[1];
    const float* v    = (const float*)d_in[2];
    const int*   mask = (const int*)d_in[3];
    const float* wq_w = (const float*)d_in[4];
    const float* wq_b = (const float*)d_in[5];
    const float* wk_w = (const float*)d_in[6];
    const float* wk_b = (const float*)d_in[7];
    const float* wv_w = (const float*)d_in[8];
    const float* wv_b = (const float*)d_in[9];
    const float* dw   = (const float*)d_in[10];
    const float* db   = (const float*)d_in[11];

    float* out = (float*)d_out;
    float* wts = out + OUT_ELEMS;

    bf16 *xqh, *xql, *xkh, *xkl, *xvh, *xvl;
    bf16 *wqh, *wql, *wkh, *wkl, *wvh, *wvl, *wdh, *wdl;
    bf16 *qph, *qpl, *kph, *kpl, *vph, *vpl, *ah, *al;
    float* attn;
    cudaGetSymbolAddress((void**)&xqh, g_xq_hi); cudaGetSymbolAddress((void**)&xql, g_xq_lo);
    cudaGetSymbolAddress((void**)&xkh, g_xk_hi); cudaGetSymbolAddress((void**)&xkl, g_xk_lo);
    cudaGetSymbolAddress((void**)&xvh, g_xv_hi); cudaGetSymbolAddress((void**)&xvl, g_xv_lo);
    cudaGetSymbolAddress((void**)&wqh, g_wq_hi); cudaGetSymbolAddress((void**)&wql, g_wq_lo);
    cudaGetSymbolAddress((void**)&wkh, g_wk_hi); cudaGetSymbolAddress((void**)&wkl, g_wk_lo);
    cudaGetSymbolAddress((void**)&wvh, g_wv_hi); cudaGetSymbolAddress((void**)&wvl, g_wv_lo);
    cudaGetSymbolAddress((void**)&wdh, g_wd_hi); cudaGetSymbolAddress((void**)&wdl, g_wd_lo);
    cudaGetSymbolAddress((void**)&qph, g_qp_hi); cudaGetSymbolAddress((void**)&qpl, g_qp_lo);
    cudaGetSymbolAddress((void**)&kph, g_kp_hi); cudaGetSymbolAddress((void**)&kpl, g_kp_lo);
    cudaGetSymbolAddress((void**)&vph, g_vp_hi); cudaGetSymbolAddress((void**)&vpl, g_vp_lo);
    cudaGetSymbolAddress((void**)&ah,  g_ah);    cudaGetSymbolAddress((void**)&al,  g_al);
    cudaGetSymbolAddress((void**)&attn, g_attn);

    cudaFuncSetAttribute(proj_kernel,   cudaFuncAttributeMaxDynamicSharedMemorySize, 81920);
    cudaFuncSetAttribute(scores_kernel, cudaFuncAttributeMaxDynamicSharedMemorySize, 73728);
    cudaFuncSetAttribute(pv_kernel,     cudaFuncAttributeMaxDynamicSharedMemorySize, 75776);

    split_kernel<<<4096, 256>>>(q, xqh, xql, 1048576);
    split_kernel<<<4096, 256>>>(k, xkh, xkl, 1048576);
    split_kernel<<<4096, 256>>>(v, xvh, xvl, 1048576);
    split_kernel<<<1024, 256>>>(wq_w, wqh, wql, 262144);
    split_kernel<<<1024, 256>>>(wk_w, wkh, wkl, 262144);
    split_kernel<<<1024, 256>>>(wv_w, wvh, wvl, 262144);
    split_kernel<<<1024, 256>>>(dw,   wdh, wdl, 262144);

    dim3 gProj(8, 32);
    proj_kernel<<<gProj, 256, 81920>>>(xqh, xql, wqh, wql, wq_b, nullptr, qph, qpl, 0);
    proj_kernel<<<gProj, 256, 81920>>>(xkh, xkl, wkh, wkl, wk_b, nullptr, kph, kpl, 0);
    proj_kernel<<<gProj, 256, 81920>>>(xvh, xvl, wvh, wvl, wv_b, nullptr, vph, vpl, 0);

    scores_kernel<<<dim3(16, 16, 32), 256, 73728>>>(qph, qpl, kph, kpl, wts);
    softmax_kernel<<<65536, 256>>>(wts, mask);
    pv_kernel<<<dim3(16, 32), 256, 75776>>>(wts, vph, vpl, attn);

    split_kernel<<<4096, 256>>>(attn, ah, al, 1048576);
    proj_kernel<<<gProj, 256, 81920>>>(ah, al, wdh, wdl, db, out, nullptr, nullptr, 2);
}